// round 1
// baseline (speedup 1.0000x reference)
#include <cuda_runtime.h>
#include <cstdint>

#define NN 100000
#define EE 1600000

// ---------------- scratch (device globals; no allocation) ----------------
__device__ int   g_is64;
__device__ int   g_deg[NN];
__device__ int   g_off[NN + 1];
__device__ int   g_cursor[NN];
__device__ int   g_csr[EE];
__device__ float g_buf[(size_t)NN * 256];  // mean1 -> mean2 -> hid (reused)
__device__ float g_h[(size_t)NN * 256];    // hidden after layer 1

// ---------------- edge index dtype detection ----------------
// int64 little-endian with values < 2^31 => every odd 32-bit word is 0.
__global__ void k_detect(const unsigned* ei) {
    if (threadIdx.x == 0) {
        int is64 = 1;
        for (int i = 0; i < 1024; i++) {
            if (ei[2 * i + 1] != 0u) { is64 = 0; break; }
        }
        g_is64 = is64;
    }
}

__device__ __forceinline__ int eidx(const void* ei, int is64, int idx) {
    if (is64) return (int)((const long long*)ei)[idx];
    return ((const int*)ei)[idx];
}

__global__ void k_zero() {
    int i = blockIdx.x * blockDim.x + threadIdx.x;
    if (i < NN) { g_deg[i] = 0; g_cursor[i] = 0; }
}

__global__ void k_hist(const void* ei) {
    int e = blockIdx.x * blockDim.x + threadIdx.x;
    if (e < EE) {
        int d = eidx(ei, g_is64, EE + e);
        atomicAdd(&g_deg[d], 1);
    }
}

// single-block chunked exclusive scan of g_deg -> g_off  (100k ints, ~98 iters)
__global__ void k_scan() {
    __shared__ int ws[32];
    __shared__ int base;
    int tid = threadIdx.x;
    int lane = tid & 31;
    int warp = tid >> 5;
    if (tid == 0) base = 0;
    __syncthreads();
    for (int start = 0; start < NN; start += 1024) {
        int i = start + tid;
        int v = (i < NN) ? g_deg[i] : 0;
        int x = v;
        #pragma unroll
        for (int o = 1; o < 32; o <<= 1) {
            int y = __shfl_up_sync(0xFFFFFFFFu, x, o);
            if (lane >= o) x += y;
        }
        if (lane == 31) ws[warp] = x;
        __syncthreads();
        if (tid < 32) {
            int s = ws[tid];
            #pragma unroll
            for (int o = 1; o < 32; o <<= 1) {
                int y = __shfl_up_sync(0xFFFFFFFFu, s, o);
                if (tid >= o) s += y;
            }
            ws[tid] = s;
        }
        __syncthreads();
        int excl = base + (warp ? ws[warp - 1] : 0) + (x - v);
        if (i < NN) g_off[i] = excl;
        __syncthreads();
        if (tid == 0) base += ws[31];
        __syncthreads();
    }
    if (threadIdx.x == 0) g_off[NN] = base;
}

__global__ void k_scatter(const void* ei) {
    int e = blockIdx.x * blockDim.x + threadIdx.x;
    if (e < EE) {
        int is64 = g_is64;
        int s = eidx(ei, is64, e);
        int d = eidx(ei, is64, EE + e);
        int p = atomicAdd(&g_cursor[d], 1);
        g_csr[g_off[d] + p] = s;
    }
}

// ---------------- mean aggregation: one warp per node ----------------
template <int F>
__global__ void k_agg(const float* __restrict__ X, float* __restrict__ out) {
    int gw = (blockIdx.x * blockDim.x + threadIdx.x) >> 5;
    int lane = threadIdx.x & 31;
    if (gw >= NN) return;
    int beg = g_off[gw], end = g_off[gw + 1];
    float4 a0 = make_float4(0.f, 0.f, 0.f, 0.f);
    float4 a1 = a0;
    const float4* base = (const float4*)X;
    for (int e = beg; e < end; e++) {
        int s = g_csr[e];
        const float4* xr = base + (size_t)s * (F / 4);
        float4 v = __ldg(&xr[lane]);
        a0.x += v.x; a0.y += v.y; a0.z += v.z; a0.w += v.w;
        if (F == 256) {
            float4 w = __ldg(&xr[lane + 32]);
            a1.x += w.x; a1.y += w.y; a1.z += w.z; a1.w += w.w;
        }
    }
    float inv = 1.0f / (float)((end - beg) > 1 ? (end - beg) : 1);
    float4* o = (float4*)(out + (size_t)gw * F);
    a0.x *= inv; a0.y *= inv; a0.z *= inv; a0.w *= inv;
    o[lane] = a0;
    if (F == 256) {
        a1.x *= inv; a1.y *= inv; a1.z *= inv; a1.w *= inv;
        o[lane + 32] = a1;
    }
}

// ---------------- fused dual-operand FP32 GEMM ----------------
// C[M, NC] = act( A1[M,K1] @ W1^T + A2[M,K2] @ W2^T + bias ),  W row-major [NC, K]
template <int BM, int BN, int BK, int TM, int TN>
__global__ void k_gemm(const float* __restrict__ A1, const float* __restrict__ W1, int K1,
                       const float* __restrict__ A2, const float* __restrict__ W2, int K2,
                       const float* __restrict__ bias, float* __restrict__ C,
                       int M, int NC, int relu) {
    constexpr int THREADS = (BM / TM) * (BN / TN);
    __shared__ float As[BK][BM];
    __shared__ float Bs[BK][BN];
    int tid = threadIdx.x;
    int tx = tid % (BN / TN);
    int ty = tid / (BN / TN);
    int row0 = blockIdx.x * BM;
    int col0 = blockIdx.y * BN;

    float acc[TM][TN];
    #pragma unroll
    for (int i = 0; i < TM; i++)
        #pragma unroll
        for (int j = 0; j < TN; j++) acc[i][j] = 0.f;

    #pragma unroll 1
    for (int pass = 0; pass < 2; pass++) {
        const float* A = pass ? A2 : A1;
        const float* W = pass ? W2 : W1;
        int K = pass ? K2 : K1;
        if (A == nullptr) break;
        for (int kt = 0; kt < K; kt += BK) {
            // load A tile (transpose to [BK][BM])
            constexpr int AV = BM * BK / 4;
            #pragma unroll
            for (int v = 0; v < AV; v += THREADS) {
                int id = v + tid;
                int m = id / (BK / 4), kq = id % (BK / 4);
                float4 val = make_float4(0.f, 0.f, 0.f, 0.f);
                int r = row0 + m;
                if (r < M) val = *(const float4*)(A + (size_t)r * K + kt + kq * 4);
                As[kq * 4 + 0][m] = val.x;
                As[kq * 4 + 1][m] = val.y;
                As[kq * 4 + 2][m] = val.z;
                As[kq * 4 + 3][m] = val.w;
            }
            // load W tile (transpose to [BK][BN]); cols always in range
            constexpr int BV = BN * BK / 4;
            #pragma unroll
            for (int v = 0; v < BV; v += THREADS) {
                int id = v + tid;
                if (id < BV) {
                    int n = id / (BK / 4), kq = id % (BK / 4);
                    float4 val = *(const float4*)(W + (size_t)(col0 + n) * K + kt + kq * 4);
                    Bs[kq * 4 + 0][n] = val.x;
                    Bs[kq * 4 + 1][n] = val.y;
                    Bs[kq * 4 + 2][n] = val.z;
                    Bs[kq * 4 + 3][n] = val.w;
                }
            }
            __syncthreads();
            #pragma unroll
            for (int kk = 0; kk < BK; kk++) {
                float a[TM], b[TN];
                #pragma unroll
                for (int i = 0; i < TM; i += 4) {
                    float4 t = *(const float4*)&As[kk][ty * TM + i];
                    a[i] = t.x; a[i + 1] = t.y; a[i + 2] = t.z; a[i + 3] = t.w;
                }
                #pragma unroll
                for (int j = 0; j < TN; j += 4) {
                    float4 t = *(const float4*)&Bs[kk][tx * TN + j];
                    b[j] = t.x; b[j + 1] = t.y; b[j + 2] = t.z; b[j + 3] = t.w;
                }
                #pragma unroll
                for (int i = 0; i < TM; i++)
                    #pragma unroll
                    for (int j = 0; j < TN; j++)
                        acc[i][j] += a[i] * b[j];
            }
            __syncthreads();
        }
    }

    // epilogue
    float bv[TN];
    #pragma unroll
    for (int j = 0; j < TN; j++) bv[j] = bias[col0 + tx * TN + j];
    #pragma unroll
    for (int i = 0; i < TM; i++) {
        int r = row0 + ty * TM + i;
        if (r < M) {
            #pragma unroll
            for (int j = 0; j < TN; j += 4) {
                float4 v;
                v.x = acc[i][j + 0] + bv[j + 0];
                v.y = acc[i][j + 1] + bv[j + 1];
                v.z = acc[i][j + 2] + bv[j + 2];
                v.w = acc[i][j + 3] + bv[j + 3];
                if (relu) {
                    v.x = fmaxf(v.x, 0.f); v.y = fmaxf(v.y, 0.f);
                    v.z = fmaxf(v.z, 0.f); v.w = fmaxf(v.w, 0.f);
                }
                *(float4*)(C + (size_t)r * NC + col0 + tx * TN + j) = v;
            }
        }
    }
}

// ---------------- launcher ----------------
extern "C" void kernel_launch(void* const* d_in, const int* in_sizes, int n_in,
                              void* d_out, int out_size) {
    const float* x     = (const float*)d_in[0];
    const void*  ei    = d_in[1];
    const float* W_l1  = (const float*)d_in[2];
    const float* b_l1  = (const float*)d_in[3];
    const float* W_r1  = (const float*)d_in[4];
    const float* W_l2  = (const float*)d_in[5];
    const float* b_l2  = (const float*)d_in[6];
    const float* W_r2  = (const float*)d_in[7];
    const float* fc1_W = (const float*)d_in[8];
    const float* fc1_b = (const float*)d_in[9];
    const float* fc2_W = (const float*)d_in[10];
    const float* fc2_b = (const float*)d_in[11];

    float* emb   = (float*)d_out;                       // [N, 64]
    float* recon = (float*)d_out + (size_t)NN * 64;     // [N, 128]

    // device-global scratch addresses
    float* buf; cudaGetSymbolAddress((void**)&buf, g_buf);
    float* h;   cudaGetSymbolAddress((void**)&h, g_h);

    // CSR build
    k_detect<<<1, 32>>>((const unsigned*)ei);
    k_zero<<<(NN + 255) / 256, 256>>>();
    k_hist<<<(EE + 255) / 256, 256>>>(ei);
    k_scan<<<1, 1024>>>();
    k_scatter<<<(EE + 255) / 256, 256>>>(ei);

    const int aggBlocks = (NN * 32 + 255) / 256;
    const int gmBlocks  = (NN + 127) / 128;

    // Layer 1: mean1 = agg(x);  h = relu(mean1 @ W_l1^T + x @ W_r1^T + b_l1)
    k_agg<128><<<aggBlocks, 256>>>(x, buf);
    k_gemm<128, 128, 16, 8, 8><<<dim3(gmBlocks, 2), 256>>>(
        buf, W_l1, 128, x, W_r1, 128, b_l1, h, NN, 256, 1);

    // Layer 2: mean2 = agg(h);  emb = mean2 @ W_l2^T + h @ W_r2^T + b_l2
    k_agg<256><<<aggBlocks, 256>>>(h, buf);
    k_gemm<128, 64, 16, 8, 4><<<dim3(gmBlocks, 1), 256>>>(
        buf, W_l2, 256, h, W_r2, 256, b_l2, emb, NN, 64, 0);

    // Decoder: hid = relu(emb @ fc1_W^T + fc1_b);  recon = hid @ fc2_W^T + fc2_b
    k_gemm<128, 128, 16, 8, 8><<<dim3(gmBlocks, 2), 256>>>(
        emb, fc1_W, 64, nullptr, nullptr, 0, fc1_b, buf, NN, 256, 1);
    k_gemm<128, 128, 16, 8, 8><<<dim3(gmBlocks, 1), 256>>>(
        buf, fc2_W, 256, nullptr, nullptr, 0, fc2_b, recon, NN, 128, 0);
}

// round 3
// speedup vs baseline: 1.0399x; 1.0399x over previous
#include <cuda_runtime.h>
#include <cstdint>

#define NN 100000
#define EE 1600000
#define NBLK ((NN + 1023) / 1024)   // 98

// ---------------- scratch (device globals; no allocation) ----------------
__device__ int   g_is64;
__device__ int   g_deg[NN];
__device__ int   g_off[NN + 1];
__device__ int   g_cursor[NN];
__device__ int   g_bsum[128];
__device__ int   g_csr[EE];
__device__ float g_buf[(size_t)NN * 256];  // mean1 -> mean2 -> hid (reused)
__device__ float g_h[(size_t)NN * 256];    // hidden after layer 1

// ---------------- edge index dtype detection ----------------
__global__ void k_detect(const unsigned* ei) {
    if (threadIdx.x == 0) {
        int is64 = 1;
        for (int i = 0; i < 1024; i++) {
            if (ei[2 * i + 1] != 0u) { is64 = 0; break; }
        }
        g_is64 = is64;
    }
}

__device__ __forceinline__ int eidx(const void* ei, int is64, int idx) {
    if (is64) return (int)((const long long*)ei)[idx];
    return ((const int*)ei)[idx];
}

__global__ void k_zero() {
    int i = blockIdx.x * blockDim.x + threadIdx.x;
    if (i < NN) { g_deg[i] = 0; g_cursor[i] = 0; }
}

__global__ void k_hist(const void* ei) {
    int e = blockIdx.x * blockDim.x + threadIdx.x;
    if (e < EE) {
        int d = eidx(ei, g_is64, EE + e);
        atomicAdd(&g_deg[d], 1);
    }
}

// ---------------- multi-block exclusive scan ----------------
__global__ void k_scan1() {
    __shared__ int ws[32];
    int tid = threadIdx.x, lane = tid & 31, warp = tid >> 5;
    int i = blockIdx.x * 1024 + tid;
    int v = (i < NN) ? g_deg[i] : 0;
    int x = v;
    #pragma unroll
    for (int o = 1; o < 32; o <<= 1) {
        int y = __shfl_up_sync(0xFFFFFFFFu, x, o);
        if (lane >= o) x += y;
    }
    if (lane == 31) ws[warp] = x;
    __syncthreads();
    if (tid < 32) {
        int s = ws[tid];
        #pragma unroll
        for (int o = 1; o < 32; o <<= 1) {
            int y = __shfl_up_sync(0xFFFFFFFFu, s, o);
            if (tid >= o) s += y;
        }
        ws[tid] = s;
    }
    __syncthreads();
    int excl = (warp ? ws[warp - 1] : 0) + (x - v);
    if (i < NN) g_off[i] = excl;
    if (tid == 0) g_bsum[blockIdx.x] = ws[31];
}

__global__ void k_scan2() {   // 1 block, 128 threads: scan the 98 block sums
    __shared__ int sh[4];
    int t = threadIdx.x, lane = t & 31, warp = t >> 5;
    int v = (t < NBLK) ? g_bsum[t] : 0;
    int x = v;
    #pragma unroll
    for (int o = 1; o < 32; o <<= 1) {
        int y = __shfl_up_sync(0xFFFFFFFFu, x, o);
        if (lane >= o) x += y;
    }
    if (lane == 31) sh[warp] = x;
    __syncthreads();
    int add = 0;
    for (int w = 0; w < warp; w++) add += sh[w];
    int excl = add + x - v;
    if (t < NBLK) g_bsum[t] = excl;
    if (t == NBLK - 1) g_off[NN] = excl + v;  // grand total
}

__global__ void k_scan3() {   // add block bases back
    int i = blockIdx.x * 1024 + threadIdx.x;
    if (i < NN) g_off[i] += g_bsum[blockIdx.x];
}

__global__ void k_scatter(const void* ei) {
    int e = blockIdx.x * blockDim.x + threadIdx.x;
    if (e < EE) {
        int is64 = g_is64;
        int s = eidx(ei, is64, e);
        int d = eidx(ei, is64, EE + e);
        int p = atomicAdd(&g_cursor[d], 1);
        g_csr[g_off[d] + p] = s;
    }
}

// ---------------- mean aggregation: one warp per node ----------------
template <int F>
__global__ void k_agg(const float* __restrict__ X, float* __restrict__ out) {
    int gw = (blockIdx.x * blockDim.x + threadIdx.x) >> 5;
    int lane = threadIdx.x & 31;
    if (gw >= NN) return;
    int beg = g_off[gw], end = g_off[gw + 1];
    float4 a0 = make_float4(0.f, 0.f, 0.f, 0.f);
    float4 a1 = a0;
    const float4* base = (const float4*)X;
    for (int e = beg; e < end; e++) {
        int s = g_csr[e];
        const float4* xr = base + (size_t)s * (F / 4);
        float4 v = __ldg(&xr[lane]);
        a0.x += v.x; a0.y += v.y; a0.z += v.z; a0.w += v.w;
        if (F == 256) {
            float4 w = __ldg(&xr[lane + 32]);
            a1.x += w.x; a1.y += w.y; a1.z += w.z; a1.w += w.w;
        }
    }
    float inv = 1.0f / (float)((end - beg) > 1 ? (end - beg) : 1);
    float4* o = (float4*)(out + (size_t)gw * F);
    a0.x *= inv; a0.y *= inv; a0.z *= inv; a0.w *= inv;
    o[lane] = a0;
    if (F == 256) {
        a1.x *= inv; a1.y *= inv; a1.z *= inv; a1.w *= inv;
        o[lane + 32] = a1;
    }
}

// ---------------- packed f32x2 FMA ----------------
__device__ __forceinline__ float2 ffma2(float2 a, float2 b, float2 c) {
    float2 d;
    asm("{\n"
        ".reg .b64 ra, rb, rc;\n"
        "mov.b64 ra, {%2,%3};\n"
        "mov.b64 rb, {%4,%5};\n"
        "mov.b64 rc, {%6,%7};\n"
        "fma.rn.f32x2 rc, ra, rb, rc;\n"
        "mov.b64 {%0,%1}, rc;\n"
        "}"
        : "=f"(d.x), "=f"(d.y)
        : "f"(a.x), "f"(a.y), "f"(b.x), "f"(b.y), "f"(c.x), "f"(c.y));
    return d;
}

// ---------------- fused dual-operand FP32 GEMM (f32x2 inner) ----------------
// C[M, NC] = act( A1[M,K1] @ W1^T + A2[M,K2] @ W2^T + bias ),  W row-major [NC, K]
template <int BM, int BN, int BK, int TM, int TN>
__global__ void k_gemm(const float* __restrict__ A1, const float* __restrict__ W1, int K1,
                       const float* __restrict__ A2, const float* __restrict__ W2, int K2,
                       const float* __restrict__ bias, float* __restrict__ C,
                       int M, int NC, int relu) {
    constexpr int THREADS = (BM / TM) * (BN / TN);
    __shared__ float As[BK][BM];
    __shared__ float Bs[BK][BN];
    int tid = threadIdx.x;
    int tx = tid % (BN / TN);
    int ty = tid / (BN / TN);
    int row0 = blockIdx.x * BM;
    int col0 = blockIdx.y * BN;

    float2 acc[TM][TN / 2];
    #pragma unroll
    for (int i = 0; i < TM; i++)
        #pragma unroll
        for (int j = 0; j < TN / 2; j++) acc[i][j] = make_float2(0.f, 0.f);

    #pragma unroll 1
    for (int pass = 0; pass < 2; pass++) {
        const float* A = pass ? A2 : A1;
        const float* W = pass ? W2 : W1;
        int K = pass ? K2 : K1;
        if (A == nullptr) break;
        for (int kt = 0; kt < K; kt += BK) {
            // load A tile (transpose to [BK][BM])
            constexpr int AV = BM * BK / 4;
            #pragma unroll
            for (int v = 0; v < AV; v += THREADS) {
                int id = v + tid;
                int m = id / (BK / 4), kq = id % (BK / 4);
                float4 val = make_float4(0.f, 0.f, 0.f, 0.f);
                int r = row0 + m;
                if (r < M) val = *(const float4*)(A + (size_t)r * K + kt + kq * 4);
                As[kq * 4 + 0][m] = val.x;
                As[kq * 4 + 1][m] = val.y;
                As[kq * 4 + 2][m] = val.z;
                As[kq * 4 + 3][m] = val.w;
            }
            // load W tile (transpose to [BK][BN]); cols always in range
            constexpr int BV = BN * BK / 4;
            #pragma unroll
            for (int v = 0; v < BV; v += THREADS) {
                int id = v + tid;
                if (id < BV) {
                    int n = id / (BK / 4), kq = id % (BK / 4);
                    float4 val = *(const float4*)(W + (size_t)(col0 + n) * K + kt + kq * 4);
                    Bs[kq * 4 + 0][n] = val.x;
                    Bs[kq * 4 + 1][n] = val.y;
                    Bs[kq * 4 + 2][n] = val.z;
                    Bs[kq * 4 + 3][n] = val.w;
                }
            }
            __syncthreads();
            #pragma unroll
            for (int kk = 0; kk < BK; kk++) {
                float a[TM];
                float2 b2[TN / 2];
                #pragma unroll
                for (int i = 0; i < TM; i += 4) {
                    float4 t = *(const float4*)&As[kk][ty * TM + i];
                    a[i] = t.x; a[i + 1] = t.y; a[i + 2] = t.z; a[i + 3] = t.w;
                }
                #pragma unroll
                for (int j = 0; j < TN; j += 4) {
                    float4 t = *(const float4*)&Bs[kk][tx * TN + j];
                    b2[j / 2]     = make_float2(t.x, t.y);
                    b2[j / 2 + 1] = make_float2(t.z, t.w);
                }
                #pragma unroll
                for (int i = 0; i < TM; i++) {
                    float2 ad = make_float2(a[i], a[i]);
                    #pragma unroll
                    for (int j = 0; j < TN / 2; j++)
                        acc[i][j] = ffma2(ad, b2[j], acc[i][j]);
                }
            }
            __syncthreads();
        }
    }

    // epilogue
    float2 bv[TN / 2];
    #pragma unroll
    for (int j = 0; j < TN / 2; j++)
        bv[j] = make_float2(bias[col0 + tx * TN + 2 * j], bias[col0 + tx * TN + 2 * j + 1]);
    #pragma unroll
    for (int i = 0; i < TM; i++) {
        int r = row0 + ty * TM + i;
        if (r < M) {
            #pragma unroll
            for (int j = 0; j < TN; j += 4) {
                float4 v;
                v.x = acc[i][j / 2].x     + bv[j / 2].x;
                v.y = acc[i][j / 2].y     + bv[j / 2].y;
                v.z = acc[i][j / 2 + 1].x + bv[j / 2 + 1].x;
                v.w = acc[i][j / 2 + 1].y + bv[j / 2 + 1].y;
                if (relu) {
                    v.x = fmaxf(v.x, 0.f); v.y = fmaxf(v.y, 0.f);
                    v.z = fmaxf(v.z, 0.f); v.w = fmaxf(v.w, 0.f);
                }
                *(float4*)(C + (size_t)r * NC + col0 + tx * TN + j) = v;
            }
        }
    }
}

// ---------------- launcher ----------------
extern "C" void kernel_launch(void* const* d_in, const int* in_sizes, int n_in,
                              void* d_out, int out_size) {
    const float* x     = (const float*)d_in[0];
    const void*  ei    = d_in[1];
    const float* W_l1  = (const float*)d_in[2];
    const float* b_l1  = (const float*)d_in[3];
    const float* W_r1  = (const float*)d_in[4];
    const float* W_l2  = (const float*)d_in[5];
    const float* b_l2  = (const float*)d_in[6];
    const float* W_r2  = (const float*)d_in[7];
    const float* fc1_W = (const float*)d_in[8];
    const float* fc1_b = (const float*)d_in[9];
    const float* fc2_W = (const float*)d_in[10];
    const float* fc2_b = (const float*)d_in[11];

    float* emb   = (float*)d_out;                       // [N, 64]
    float* recon = (float*)d_out + (size_t)NN * 64;     // [N, 128]

    float* buf; cudaGetSymbolAddress((void**)&buf, g_buf);
    float* h;   cudaGetSymbolAddress((void**)&h, g_h);

    // CSR build
    k_detect<<<1, 32>>>((const unsigned*)ei);
    k_zero<<<(NN + 255) / 256, 256>>>();
    k_hist<<<(EE + 255) / 256, 256>>>(ei);
    k_scan1<<<NBLK, 1024>>>();
    k_scan2<<<1, 128>>>();
    k_scan3<<<NBLK, 1024>>>();
    k_scatter<<<(EE + 255) / 256, 256>>>(ei);

    const int aggBlocks = (NN * 32 + 255) / 256;
    const int gmBlocks  = (NN + 127) / 128;

    // Layer 1: mean1 = agg(x);  h = relu(mean1 @ W_l1^T + x @ W_r1^T + b_l1)
    k_agg<128><<<aggBlocks, 256>>>(x, buf);
    k_gemm<128, 128, 16, 8, 8><<<dim3(gmBlocks, 2), 256>>>(
        buf, W_l1, 128, x, W_r1, 128, b_l1, h, NN, 256, 1);

    // Layer 2: mean2 = agg(h);  emb = mean2 @ W_l2^T + h @ W_r2^T + b_l2
    k_agg<256><<<aggBlocks, 256>>>(h, buf);
    k_gemm<128, 64, 16, 8, 4><<<dim3(gmBlocks, 1), 256>>>(
        buf, W_l2, 256, h, W_r2, 256, b_l2, emb, NN, 64, 0);

    // Decoder: hid = relu(emb @ fc1_W^T + fc1_b);  recon = hid @ fc2_W^T + fc2_b
    k_gemm<128, 128, 16, 8, 8><<<dim3(gmBlocks, 2), 256>>>(
        emb, fc1_W, 64, nullptr, nullptr, 0, fc1_b, buf, NN, 256, 1);
    k_gemm<128, 128, 16, 8, 8><<<dim3(gmBlocks, 1), 256>>>(
        buf, fc2_W, 256, nullptr, nullptr, 0, fc2_b, recon, NN, 128, 0);
}

// round 5
// speedup vs baseline: 1.8216x; 1.7517x over previous
#include <cuda_runtime.h>
#include <cuda_bf16.h>
#include <cstdint>

#define NN 100000
#define EE 1600000
#define NBLK ((NN + 1023) / 1024)   // 98
#define WTOT 147456                  // total weight elements across 6 matrices

// ---------------- scratch (device globals; no allocation) ----------------
__device__ int   g_is64;
__device__ int   g_deg[NN];
__device__ int   g_off[NN + 1];   // per-block local exclusive prefix
__device__ int   g_cursor[NN];
__device__ int   g_bsum[128];     // block bases (after k_scan2)
__device__ int   g_csr[EE];
__device__ float g_buf[(size_t)NN * 256];  // mean1 -> mean2 -> hid (reused)
__device__ float g_h[(size_t)NN * 256];    // hidden after layer 1
__device__ __nv_bfloat16 g_whi[WTOT];
__device__ __nv_bfloat16 g_wlo[WTOT];

__device__ __forceinline__ int OFF(int i) { return g_off[i] + g_bsum[i >> 10]; }

// ---------------- prep: split weights to bf16 hi/lo + zero + dtype detect ----
__global__ void k_prep(const unsigned* ei,
                       const float* Wl1, const float* Wr1,
                       const float* Wl2, const float* Wr2,
                       const float* fc1, const float* fc2) {
    int i = blockIdx.x * blockDim.x + threadIdx.x;
    if (i == 0) {
        int is64 = 1;
        for (int t = 0; t < 1024; t++)
            if (ei[2 * t + 1] != 0u) { is64 = 0; break; }
        g_is64 = is64;
    }
    if (i < NN) { g_deg[i] = 0; g_cursor[i] = 0; }
    if (i < WTOT) {
        const float* src; int off;
        if      (i < 32768)  { src = Wl1; off = 0; }
        else if (i < 65536)  { src = Wr1; off = 32768; }
        else if (i < 81920)  { src = Wl2; off = 65536; }
        else if (i < 98304)  { src = Wr2; off = 81920; }
        else if (i < 114688) { src = fc1; off = 98304; }
        else                 { src = fc2; off = 114688; }
        float a = src[i - off];
        __nv_bfloat16 h = __float2bfloat16(a);
        g_whi[i] = h;
        g_wlo[i] = __float2bfloat16(a - __bfloat162float(h));
    }
}

__device__ __forceinline__ int eidx(const void* ei, int is64, int idx) {
    if (is64) return (int)((const long long*)ei)[idx];
    return ((const int*)ei)[idx];
}

__global__ void k_hist(const void* ei) {
    int e = blockIdx.x * blockDim.x + threadIdx.x;
    if (e < EE) atomicAdd(&g_deg[eidx(ei, g_is64, EE + e)], 1);
}

// ---------------- multi-block exclusive scan (local) ----------------
__global__ void k_scan1() {
    __shared__ int ws[32];
    int tid = threadIdx.x, lane = tid & 31, warp = tid >> 5;
    int i = blockIdx.x * 1024 + tid;
    int v = (i < NN) ? g_deg[i] : 0;
    int x = v;
    #pragma unroll
    for (int o = 1; o < 32; o <<= 1) {
        int y = __shfl_up_sync(0xFFFFFFFFu, x, o);
        if (lane >= o) x += y;
    }
    if (lane == 31) ws[warp] = x;
    __syncthreads();
    if (tid < 32) {
        int s = ws[tid];
        #pragma unroll
        for (int o = 1; o < 32; o <<= 1) {
            int y = __shfl_up_sync(0xFFFFFFFFu, s, o);
            if (tid >= o) s += y;
        }
        ws[tid] = s;
    }
    __syncthreads();
    int excl = (warp ? ws[warp - 1] : 0) + (x - v);
    if (i <= NN) g_off[i] = excl;           // include i == NN sentinel
    if (tid == 0) g_bsum[blockIdx.x] = ws[31];
}

__global__ void k_scan2() {   // 1 block, 128 threads: scan the 98 block sums
    __shared__ int sh[4];
    int t = threadIdx.x, lane = t & 31, warp = t >> 5;
    int v = (t < NBLK) ? g_bsum[t] : 0;
    int x = v;
    #pragma unroll
    for (int o = 1; o < 32; o <<= 1) {
        int y = __shfl_up_sync(0xFFFFFFFFu, x, o);
        if (lane >= o) x += y;
    }
    if (lane == 31) sh[warp] = x;
    __syncthreads();
    int add = 0;
    for (int w = 0; w < warp; w++) add += sh[w];
    if (t < NBLK) g_bsum[t] = add + x - v;   // exclusive base per block
}

__global__ void k_scatter(const void* ei) {
    int e = blockIdx.x * blockDim.x + threadIdx.x;
    if (e < EE) {
        int is64 = g_is64;
        int s = eidx(ei, is64, e);
        int d = eidx(ei, is64, EE + e);
        int p = atomicAdd(&g_cursor[d], 1);
        g_csr[OFF(d) + p] = s;
    }
}

// ---------------- mean aggregation: one warp per node ----------------
template <int F>
__global__ void k_agg(const float* __restrict__ X, float* __restrict__ out) {
    int gw = (blockIdx.x * blockDim.x + threadIdx.x) >> 5;
    int lane = threadIdx.x & 31;
    if (gw >= NN) return;
    int beg = OFF(gw), end = OFF(gw + 1);
    float4 a0 = make_float4(0.f, 0.f, 0.f, 0.f);
    float4 a1 = a0;
    const float4* base = (const float4*)X;
    for (int e = beg; e < end; e++) {
        int s = g_csr[e];
        const float4* xr = base + (size_t)s * (F / 4);
        float4 v = __ldg(&xr[lane]);
        a0.x += v.x; a0.y += v.y; a0.z += v.z; a0.w += v.w;
        if (F == 256) {
            float4 w = __ldg(&xr[lane + 32]);
            a1.x += w.x; a1.y += w.y; a1.z += w.z; a1.w += w.w;
        }
    }
    float inv = 1.0f / (float)((end - beg) > 1 ? (end - beg) : 1);
    float4* o = (float4*)(out + (size_t)gw * F);
    a0.x *= inv; a0.y *= inv; a0.z *= inv; a0.w *= inv;
    o[lane] = a0;
    if (F == 256) {
        a1.x *= inv; a1.y *= inv; a1.z *= inv; a1.w *= inv;
        o[lane + 32] = a1;
    }
}

// ---------------- tensor-core GEMM: bf16 hi/lo split, fp32 accum ----------
__device__ __forceinline__ void mma_bf16(float4& c, const unsigned* a, const unsigned* b) {
    asm volatile(
        "mma.sync.aligned.m16n8k16.row.col.f32.bf16.bf16.f32 "
        "{%0,%1,%2,%3}, {%4,%5,%6,%7}, {%8,%9}, {%0,%1,%2,%3};"
        : "+f"(c.x), "+f"(c.y), "+f"(c.z), "+f"(c.w)
        : "r"(a[0]), "r"(a[1]), "r"(a[2]), "r"(a[3]), "r"(b[0]), "r"(b[1]));
}

__device__ __forceinline__ void ldsm4(unsigned* r, const __nv_bfloat16* p) {
    unsigned addr = (unsigned)__cvta_generic_to_shared(p);
    asm volatile("ldmatrix.sync.aligned.m8n8.x4.shared.b16 {%0,%1,%2,%3}, [%4];"
                 : "=r"(r[0]), "=r"(r[1]), "=r"(r[2]), "=r"(r[3]) : "r"(addr));
}

// C[M, NC] = act( A1 @ W1^T + A2 @ W2^T + bias ), W split into (hi, lo) bf16.
// BM=128, BK=32. Warp tile 64x32. NWN warps along N (BN = 32*NWN), 2 along M.
template <int BN, int NWN>
__global__ __launch_bounds__(NWN * 64) void k_gemm(
    const float* __restrict__ A1, const __nv_bfloat16* __restrict__ W1h,
    const __nv_bfloat16* __restrict__ W1l, int K1,
    const float* __restrict__ A2, const __nv_bfloat16* __restrict__ W2h,
    const __nv_bfloat16* __restrict__ W2l, int K2,
    const float* __restrict__ bias, float* __restrict__ C,
    int M, int NC, int relu) {
    constexpr int THREADS = NWN * 64;
    constexpr int LDA = 40;  // halves; 80B row stride -> conflict-free ldmatrix
    __shared__ __nv_bfloat16 Ah[128 * LDA], Al[128 * LDA];
    __shared__ __nv_bfloat16 Bh[BN * LDA],  Bl[BN * LDA];

    int tid = threadIdx.x, lane = tid & 31, w = tid >> 5;
    int g = lane >> 2, tg = lane & 3;
    int lr = lane & 15, lc = (lane >> 4) * 8;          // ldmatrix addressing
    int wm0 = (w / NWN) * 64, wn0 = (w % NWN) * 32;
    int row0 = blockIdx.x * 128, col0 = blockIdx.y * BN;

    float4 acc[4][4];
    #pragma unroll
    for (int i = 0; i < 4; i++)
        #pragma unroll
        for (int j = 0; j < 4; j++) acc[i][j] = make_float4(0.f, 0.f, 0.f, 0.f);

    #pragma unroll 1
    for (int pass = 0; pass < 2; pass++) {
        const float* A = pass ? A2 : A1;
        if (A == nullptr) break;
        const __nv_bfloat16* Wh = pass ? W2h : W1h;
        const __nv_bfloat16* Wl_ = pass ? W2l : W1l;
        int K = pass ? K2 : K1;
        for (int kt = 0; kt < K; kt += 32) {
            // A tile: load fp32, split to hi/lo bf16 in smem
            #pragma unroll
            for (int id = tid; id < 1024; id += THREADS) {
                int m = id >> 3, kq = id & 7;
                int r = row0 + m;
                float4 v = make_float4(0.f, 0.f, 0.f, 0.f);
                if (r < M) v = *(const float4*)(A + (size_t)r * K + kt + kq * 4);
                __nv_bfloat16 h0 = __float2bfloat16(v.x), h1 = __float2bfloat16(v.y);
                __nv_bfloat16 h2 = __float2bfloat16(v.z), h3 = __float2bfloat16(v.w);
                *(__nv_bfloat162*)&Ah[m * LDA + kq * 4]     = __halves2bfloat162(h0, h1);
                *(__nv_bfloat162*)&Ah[m * LDA + kq * 4 + 2] = __halves2bfloat162(h2, h3);
                __nv_bfloat16 l0 = __float2bfloat16(v.x - __bfloat162float(h0));
                __nv_bfloat16 l1 = __float2bfloat16(v.y - __bfloat162float(h1));
                __nv_bfloat16 l2 = __float2bfloat16(v.z - __bfloat162float(h2));
                __nv_bfloat16 l3 = __float2bfloat16(v.w - __bfloat162float(h3));
                *(__nv_bfloat162*)&Al[m * LDA + kq * 4]     = __halves2bfloat162(l0, l1);
                *(__nv_bfloat162*)&Al[m * LDA + kq * 4 + 2] = __halves2bfloat162(l2, l3);
            }
            // B tile: pre-split bf16 weights, 16B vector copies
            #pragma unroll
            for (int id = tid; id < BN * 4; id += THREADS) {
                int n = id >> 2, kq = id & 3;
                *(uint4*)&Bh[n * LDA + kq * 8] =
                    *(const uint4*)(Wh + (size_t)(col0 + n) * K + kt + kq * 8);
                *(uint4*)&Bl[n * LDA + kq * 8] =
                    *(const uint4*)(Wl_ + (size_t)(col0 + n) * K + kt + kq * 8);
            }
            __syncthreads();
            #pragma unroll
            for (int ks = 0; ks < 2; ks++) {
                int k0 = ks * 16;
                unsigned Afh[4][4], Afl[4][4], Bfh[4][2], Bfl[4][2];
                #pragma unroll
                for (int mi = 0; mi < 4; mi++) {
                    int ro = (wm0 + mi * 16 + lr) * LDA + k0 + lc;
                    ldsm4(Afh[mi], &Ah[ro]);
                    ldsm4(Afl[mi], &Al[ro]);
                }
                #pragma unroll
                for (int ni = 0; ni < 4; ni++) {
                    int n = wn0 + ni * 8 + g;
                    Bfh[ni][0] = *(const unsigned*)&Bh[n * LDA + k0 + tg * 2];
                    Bfh[ni][1] = *(const unsigned*)&Bh[n * LDA + k0 + 8 + tg * 2];
                    Bfl[ni][0] = *(const unsigned*)&Bl[n * LDA + k0 + tg * 2];
                    Bfl[ni][1] = *(const unsigned*)&Bl[n * LDA + k0 + 8 + tg * 2];
                }
                #pragma unroll
                for (int mi = 0; mi < 4; mi++)
                    #pragma unroll
                    for (int ni = 0; ni < 4; ni++) {
                        mma_bf16(acc[mi][ni], Afh[mi], Bfh[ni]);
                        mma_bf16(acc[mi][ni], Afh[mi], Bfl[ni]);
                        mma_bf16(acc[mi][ni], Afl[mi], Bfh[ni]);
                    }
            }
            __syncthreads();
        }
    }

    // epilogue
    #pragma unroll
    for (int ni = 0; ni < 4; ni++) {
        int col = col0 + wn0 + ni * 8 + tg * 2;
        float b0 = bias[col], b1 = bias[col + 1];
        #pragma unroll
        for (int mi = 0; mi < 4; mi++) {
            int ra = row0 + wm0 + mi * 16 + g;
            float2 v0 = make_float2(acc[mi][ni].x + b0, acc[mi][ni].y + b1);
            float2 v1 = make_float2(acc[mi][ni].z + b0, acc[mi][ni].w + b1);
            if (relu) {
                v0.x = fmaxf(v0.x, 0.f); v0.y = fmaxf(v0.y, 0.f);
                v1.x = fmaxf(v1.x, 0.f); v1.y = fmaxf(v1.y, 0.f);
            }
            if (ra < M)     *(float2*)(C + (size_t)ra * NC + col) = v0;
            if (ra + 8 < M) *(float2*)(C + (size_t)(ra + 8) * NC + col) = v1;
        }
    }
}

// ---------------- launcher ----------------
extern "C" void kernel_launch(void* const* d_in, const int* in_sizes, int n_in,
                              void* d_out, int out_size) {
    const float* x     = (const float*)d_in[0];
    const void*  ei    = d_in[1];
    const float* W_l1  = (const float*)d_in[2];
    const float* b_l1  = (const float*)d_in[3];
    const float* W_r1  = (const float*)d_in[4];
    const float* W_l2  = (const float*)d_in[5];
    const float* b_l2  = (const float*)d_in[6];
    const float* W_r2  = (const float*)d_in[7];
    const float* fc1_W = (const float*)d_in[8];
    const float* fc1_b = (const float*)d_in[9];
    const float* fc2_W = (const float*)d_in[10];
    const float* fc2_b = (const float*)d_in[11];

    float* emb   = (float*)d_out;                       // [N, 64]
    float* recon = (float*)d_out + (size_t)NN * 64;     // [N, 128]

    float* buf; cudaGetSymbolAddress((void**)&buf, g_buf);
    float* h;   cudaGetSymbolAddress((void**)&h, g_h);
    __nv_bfloat16* whi; cudaGetSymbolAddress((void**)&whi, g_whi);
    __nv_bfloat16* wlo; cudaGetSymbolAddress((void**)&wlo, g_wlo);

    // CSR build + weight split
    k_prep<<<(WTOT + 255) / 256, 256>>>((const unsigned*)ei, W_l1, W_r1, W_l2, W_r2, fc1_W, fc2_W);
    k_hist<<<(EE + 255) / 256, 256>>>(ei);
    k_scan1<<<NBLK, 1024>>>();
    k_scan2<<<1, 128>>>();
    k_scatter<<<(EE + 255) / 256, 256>>>(ei);

    const int aggBlocks = (NN * 32 + 255) / 256;
    const int gmBlocks  = (NN + 127) / 128;

    // weight segment offsets in g_whi / g_wlo
    const int oWl1 = 0, oWr1 = 32768, oWl2 = 65536, oWr2 = 81920, oF1 = 98304, oF2 = 114688;

    // Layer 1: mean1 = agg(x);  h = relu(mean1 @ W_l1^T + x @ W_r1^T + b_l1)
    k_agg<128><<<aggBlocks, 256>>>(x, buf);
    k_gemm<128, 4><<<dim3(gmBlocks, 2), 256>>>(
        buf, whi + oWl1, wlo + oWl1, 128,
        x,   whi + oWr1, wlo + oWr1, 128, b_l1, h, NN, 256, 1);

    // Layer 2: mean2 = agg(h);  emb = mean2 @ W_l2^T + h @ W_r2^T + b_l2
    k_agg<256><<<aggBlocks, 256>>>(h, buf);
    k_gemm<64, 2><<<dim3(gmBlocks, 1), 128>>>(
        buf, whi + oWl2, wlo + oWl2, 256,
        h,   whi + oWr2, wlo + oWr2, 256, b_l2, emb, NN, 64, 0);

    // Decoder: hid = relu(emb @ fc1_W^T + fc1_b);  recon = hid @ fc2_W^T + fc2_b
    k_gemm<128, 4><<<dim3(gmBlocks, 2), 256>>>(
        emb, whi + oF1, wlo + oF1, 64,
        nullptr, nullptr, nullptr, 0, fc1_b, buf, NN, 256, 1);
    k_gemm<128, 4><<<dim3(gmBlocks, 1), 256>>>(
        buf, whi + oF2, wlo + oF2, 256,
        nullptr, nullptr, nullptr, 0, fc2_b, recon, NN, 128, 0);
}

// round 6
// speedup vs baseline: 2.1435x; 1.1767x over previous
#include <cuda_runtime.h>
#include <cuda_bf16.h>
#include <cstdint>

#define NN 100000
#define EE 1600000
#define NBLK ((NN + 1023) / 1024)   // 98
#define WTOT 147456                  // total weight elements across 6 matrices

// ---------------- scratch (device globals; no allocation) ----------------
__device__ int   g_is64;
__device__ int   g_deg[NN];
__device__ int   g_off[NN + 1];   // per-block local exclusive prefix
__device__ int   g_cursor[NN];
__device__ int   g_bsum[128];     // block bases (after k_scan2)
__device__ int   g_csr[EE];
__device__ float g_buf[(size_t)NN * 256];  // mean1 -> pq -> hid (reused)
__device__ float g_h[(size_t)NN * 256];    // hidden after layer 1
__device__ float g_bias2[128];             // [0(64) | b_l2(64)]
__device__ __nv_bfloat16 g_whi[WTOT];
__device__ __nv_bfloat16 g_wlo[WTOT];

__device__ __forceinline__ int OFF(int i) { return g_off[i] + g_bsum[i >> 10]; }

// ---------------- prep: split weights to bf16 hi/lo + zero + dtype detect ----
__global__ void k_prep(const unsigned* ei,
                       const float* Wl1, const float* Wr1,
                       const float* Wl2, const float* Wr2,
                       const float* fc1, const float* fc2,
                       const float* bl2) {
    int i = blockIdx.x * blockDim.x + threadIdx.x;
    if (i == 0) {
        int is64 = 1;
        for (int t = 0; t < 1024; t++)
            if (ei[2 * t + 1] != 0u) { is64 = 0; break; }
        g_is64 = is64;
    }
    if (i < NN) { g_deg[i] = 0; g_cursor[i] = 0; }
    if (i < 128) g_bias2[i] = (i < 64) ? 0.f : bl2[i - 64];
    if (i < WTOT) {
        const float* src; int off;
        if      (i < 32768)  { src = Wl1; off = 0; }
        else if (i < 65536)  { src = Wr1; off = 32768; }
        else if (i < 81920)  { src = Wl2; off = 65536; }
        else if (i < 98304)  { src = Wr2; off = 81920; }
        else if (i < 114688) { src = fc1; off = 98304; }
        else                 { src = fc2; off = 114688; }
        float a = src[i - off];
        __nv_bfloat16 h = __float2bfloat16(a);
        g_whi[i] = h;
        g_wlo[i] = __float2bfloat16(a - __bfloat162float(h));
    }
}

__device__ __forceinline__ int eidx(const void* ei, int is64, int idx) {
    if (is64) return (int)((const long long*)ei)[idx];
    return ((const int*)ei)[idx];
}

__global__ void k_hist(const void* ei) {
    int e = blockIdx.x * blockDim.x + threadIdx.x;
    if (e < EE) atomicAdd(&g_deg[eidx(ei, g_is64, EE + e)], 1);
}

// ---------------- multi-block exclusive scan (local) ----------------
__global__ void k_scan1() {
    __shared__ int ws[32];
    int tid = threadIdx.x, lane = tid & 31, warp = tid >> 5;
    int i = blockIdx.x * 1024 + tid;
    int v = (i < NN) ? g_deg[i] : 0;
    int x = v;
    #pragma unroll
    for (int o = 1; o < 32; o <<= 1) {
        int y = __shfl_up_sync(0xFFFFFFFFu, x, o);
        if (lane >= o) x += y;
    }
    if (lane == 31) ws[warp] = x;
    __syncthreads();
    if (tid < 32) {
        int s = ws[tid];
        #pragma unroll
        for (int o = 1; o < 32; o <<= 1) {
            int y = __shfl_up_sync(0xFFFFFFFFu, s, o);
            if (tid >= o) s += y;
        }
        ws[tid] = s;
    }
    __syncthreads();
    int excl = (warp ? ws[warp - 1] : 0) + (x - v);
    if (i <= NN) g_off[i] = excl;           // include i == NN sentinel
    if (tid == 0) g_bsum[blockIdx.x] = ws[31];
}

__global__ void k_scan2() {   // 1 block, 128 threads: scan the 98 block sums
    __shared__ int sh[4];
    int t = threadIdx.x, lane = t & 31, warp = t >> 5;
    int v = (t < NBLK) ? g_bsum[t] : 0;
    int x = v;
    #pragma unroll
    for (int o = 1; o < 32; o <<= 1) {
        int y = __shfl_up_sync(0xFFFFFFFFu, x, o);
        if (lane >= o) x += y;
    }
    if (lane == 31) sh[warp] = x;
    __syncthreads();
    int add = 0;
    for (int w = 0; w < warp; w++) add += sh[w];
    if (t < NBLK) g_bsum[t] = add + x - v;   // exclusive base per block
}

__global__ void k_scatter(const void* ei) {
    int e = blockIdx.x * blockDim.x + threadIdx.x;
    if (e < EE) {
        int is64 = g_is64;
        int s = eidx(ei, is64, e);
        int d = eidx(ei, is64, EE + e);
        int p = atomicAdd(&g_cursor[d], 1);
        g_csr[OFF(d) + p] = s;
    }
}

// ---------------- mean aggregation (F=128): warp/node, 4-way MLP ----------
__global__ void k_agg128(const float* __restrict__ X, float* __restrict__ out) {
    int gw = (blockIdx.x * blockDim.x + threadIdx.x) >> 5;
    int lane = threadIdx.x & 31;
    if (gw >= NN) return;
    int beg = OFF(gw), end = OFF(gw + 1);
    float4 a0 = make_float4(0.f, 0.f, 0.f, 0.f), a1 = a0, a2 = a0, a3 = a0;
    const float4* base = (const float4*)X;
    int e = beg;
    for (; e + 4 <= end; e += 4) {
        int s0 = g_csr[e], s1 = g_csr[e + 1], s2 = g_csr[e + 2], s3 = g_csr[e + 3];
        float4 v0 = __ldg(base + (size_t)s0 * 32 + lane);
        float4 v1 = __ldg(base + (size_t)s1 * 32 + lane);
        float4 v2 = __ldg(base + (size_t)s2 * 32 + lane);
        float4 v3 = __ldg(base + (size_t)s3 * 32 + lane);
        a0.x += v0.x; a0.y += v0.y; a0.z += v0.z; a0.w += v0.w;
        a1.x += v1.x; a1.y += v1.y; a1.z += v1.z; a1.w += v1.w;
        a2.x += v2.x; a2.y += v2.y; a2.z += v2.z; a2.w += v2.w;
        a3.x += v3.x; a3.y += v3.y; a3.z += v3.z; a3.w += v3.w;
    }
    for (; e < end; e++) {
        float4 v = __ldg(base + (size_t)g_csr[e] * 32 + lane);
        a0.x += v.x; a0.y += v.y; a0.z += v.z; a0.w += v.w;
    }
    a0.x += a1.x + a2.x + a3.x; a0.y += a1.y + a2.y + a3.y;
    a0.z += a1.z + a2.z + a3.z; a0.w += a1.w + a2.w + a3.w;
    float inv = 1.0f / (float)((end - beg) > 1 ? (end - beg) : 1);
    a0.x *= inv; a0.y *= inv; a0.z *= inv; a0.w *= inv;
    ((float4*)(out + (size_t)gw * 128))[lane] = a0;
}

// ---- layer-2 fused agg: emb[i] = mean_j p[j] + q[i];  pq rows = [p(64)|q(64)]
__global__ void k_agg_add(const float* __restrict__ pq, float* __restrict__ emb) {
    int gw = (blockIdx.x * blockDim.x + threadIdx.x) >> 5;
    int lane = threadIdx.x & 31;
    if (gw >= NN) return;
    int beg = OFF(gw), end = OFF(gw + 1);
    float2 a0 = make_float2(0.f, 0.f), a1 = a0, a2 = a0, a3 = a0;
    const float2* base = (const float2*)pq;   // row stride 64 float2
    int e = beg;
    for (; e + 4 <= end; e += 4) {
        int s0 = g_csr[e], s1 = g_csr[e + 1], s2 = g_csr[e + 2], s3 = g_csr[e + 3];
        float2 v0 = __ldg(base + (size_t)s0 * 64 + lane);
        float2 v1 = __ldg(base + (size_t)s1 * 64 + lane);
        float2 v2 = __ldg(base + (size_t)s2 * 64 + lane);
        float2 v3 = __ldg(base + (size_t)s3 * 64 + lane);
        a0.x += v0.x; a0.y += v0.y;
        a1.x += v1.x; a1.y += v1.y;
        a2.x += v2.x; a2.y += v2.y;
        a3.x += v3.x; a3.y += v3.y;
    }
    for (; e < end; e++) {
        float2 v = __ldg(base + (size_t)g_csr[e] * 64 + lane);
        a0.x += v.x; a0.y += v.y;
    }
    a0.x += a1.x + a2.x + a3.x;
    a0.y += a1.y + a2.y + a3.y;
    float inv = 1.0f / (float)((end - beg) > 1 ? (end - beg) : 1);
    float2 q = __ldg(base + (size_t)gw * 64 + 32 + lane);
    float2 r = make_float2(a0.x * inv + q.x, a0.y * inv + q.y);
    *(float2*)(emb + (size_t)gw * 64 + lane * 2) = r;
}

// ---------------- tensor-core GEMM: bf16 hi/lo split, fp32 accum ----------
__device__ __forceinline__ void mma_bf16(float4& c, const unsigned* a, const unsigned* b) {
    asm volatile(
        "mma.sync.aligned.m16n8k16.row.col.f32.bf16.bf16.f32 "
        "{%0,%1,%2,%3}, {%4,%5,%6,%7}, {%8,%9}, {%0,%1,%2,%3};"
        : "+f"(c.x), "+f"(c.y), "+f"(c.z), "+f"(c.w)
        : "r"(a[0]), "r"(a[1]), "r"(a[2]), "r"(a[3]), "r"(b[0]), "r"(b[1]));
}

__device__ __forceinline__ void ldsm4(unsigned* r, const __nv_bfloat16* p) {
    unsigned addr = (unsigned)__cvta_generic_to_shared(p);
    asm volatile("ldmatrix.sync.aligned.m8n8.x4.shared.b16 {%0,%1,%2,%3}, [%4];"
                 : "=r"(r[0]), "=r"(r[1]), "=r"(r[2]), "=r"(r[3]) : "r"(addr));
}

// C[M, NC] = act( A1 @ W1^T + A2 @ W2^T + bias ), W split into (hi, lo) bf16.
// BM=128, BK=32. Warp tile 64x32. NWN warps along N (BN = 32*NWN), 2 along M.
template <int BN, int NWN>
__global__ __launch_bounds__(NWN * 64) void k_gemm(
    const float* __restrict__ A1, const __nv_bfloat16* __restrict__ W1h,
    const __nv_bfloat16* __restrict__ W1l, int K1,
    const float* __restrict__ A2, const __nv_bfloat16* __restrict__ W2h,
    const __nv_bfloat16* __restrict__ W2l, int K2,
    const float* __restrict__ bias, float* __restrict__ C,
    int M, int NC, int relu) {
    constexpr int THREADS = NWN * 64;
    constexpr int LDA = 40;  // halves; 80B row stride -> conflict-free ldmatrix
    __shared__ __nv_bfloat16 Ah[128 * LDA], Al[128 * LDA];
    __shared__ __nv_bfloat16 Bh[BN * LDA],  Bl[BN * LDA];

    int tid = threadIdx.x, lane = tid & 31, w = tid >> 5;
    int g = lane >> 2, tg = lane & 3;
    int lr = lane & 15, lc = (lane >> 4) * 8;          // ldmatrix addressing
    int wm0 = (w / NWN) * 64, wn0 = (w % NWN) * 32;
    int row0 = blockIdx.x * 128, col0 = blockIdx.y * BN;

    float4 acc[4][4];
    #pragma unroll
    for (int i = 0; i < 4; i++)
        #pragma unroll
        for (int j = 0; j < 4; j++) acc[i][j] = make_float4(0.f, 0.f, 0.f, 0.f);

    #pragma unroll 1
    for (int pass = 0; pass < 2; pass++) {
        const float* A = pass ? A2 : A1;
        if (A == nullptr) break;
        const __nv_bfloat16* Wh = pass ? W2h : W1h;
        const __nv_bfloat16* Wl_ = pass ? W2l : W1l;
        int K = pass ? K2 : K1;
        for (int kt = 0; kt < K; kt += 32) {
            // A tile: load fp32, split to hi/lo bf16 in smem
            #pragma unroll
            for (int id = tid; id < 1024; id += THREADS) {
                int m = id >> 3, kq = id & 7;
                int r = row0 + m;
                float4 v = make_float4(0.f, 0.f, 0.f, 0.f);
                if (r < M) v = *(const float4*)(A + (size_t)r * K + kt + kq * 4);
                __nv_bfloat16 h0 = __float2bfloat16(v.x), h1 = __float2bfloat16(v.y);
                __nv_bfloat16 h2 = __float2bfloat16(v.z), h3 = __float2bfloat16(v.w);
                *(__nv_bfloat162*)&Ah[m * LDA + kq * 4]     = __halves2bfloat162(h0, h1);
                *(__nv_bfloat162*)&Ah[m * LDA + kq * 4 + 2] = __halves2bfloat162(h2, h3);
                __nv_bfloat16 l0 = __float2bfloat16(v.x - __bfloat162float(h0));
                __nv_bfloat16 l1 = __float2bfloat16(v.y - __bfloat162float(h1));
                __nv_bfloat16 l2 = __float2bfloat16(v.z - __bfloat162float(h2));
                __nv_bfloat16 l3 = __float2bfloat16(v.w - __bfloat162float(h3));
                *(__nv_bfloat162*)&Al[m * LDA + kq * 4]     = __halves2bfloat162(l0, l1);
                *(__nv_bfloat162*)&Al[m * LDA + kq * 4 + 2] = __halves2bfloat162(l2, l3);
            }
            // B tile: pre-split bf16 weights, 16B vector copies
            #pragma unroll
            for (int id = tid; id < BN * 4; id += THREADS) {
                int n = id >> 2, kq = id & 3;
                *(uint4*)&Bh[n * LDA + kq * 8] =
                    *(const uint4*)(Wh + (size_t)(col0 + n) * K + kt + kq * 8);
                *(uint4*)&Bl[n * LDA + kq * 8] =
                    *(const uint4*)(Wl_ + (size_t)(col0 + n) * K + kt + kq * 8);
            }
            __syncthreads();
            #pragma unroll
            for (int ks = 0; ks < 2; ks++) {
                int k0 = ks * 16;
                unsigned Afh[4][4], Afl[4][4], Bfh[4][2], Bfl[4][2];
                #pragma unroll
                for (int mi = 0; mi < 4; mi++) {
                    int ro = (wm0 + mi * 16 + lr) * LDA + k0 + lc;
                    ldsm4(Afh[mi], &Ah[ro]);
                    ldsm4(Afl[mi], &Al[ro]);
                }
                #pragma unroll
                for (int ni = 0; ni < 4; ni++) {
                    int n = wn0 + ni * 8 + g;
                    Bfh[ni][0] = *(const unsigned*)&Bh[n * LDA + k0 + tg * 2];
                    Bfh[ni][1] = *(const unsigned*)&Bh[n * LDA + k0 + 8 + tg * 2];
                    Bfl[ni][0] = *(const unsigned*)&Bl[n * LDA + k0 + tg * 2];
                    Bfl[ni][1] = *(const unsigned*)&Bl[n * LDA + k0 + 8 + tg * 2];
                }
                #pragma unroll
                for (int mi = 0; mi < 4; mi++)
                    #pragma unroll
                    for (int ni = 0; ni < 4; ni++) {
                        mma_bf16(acc[mi][ni], Afh[mi], Bfh[ni]);
                        mma_bf16(acc[mi][ni], Afh[mi], Bfl[ni]);
                        mma_bf16(acc[mi][ni], Afl[mi], Bfh[ni]);
                    }
            }
            __syncthreads();
        }
    }

    // epilogue
    #pragma unroll
    for (int ni = 0; ni < 4; ni++) {
        int col = col0 + wn0 + ni * 8 + tg * 2;
        float b0 = bias[col], b1 = bias[col + 1];
        #pragma unroll
        for (int mi = 0; mi < 4; mi++) {
            int ra = row0 + wm0 + mi * 16 + g;
            float2 v0 = make_float2(acc[mi][ni].x + b0, acc[mi][ni].y + b1);
            float2 v1 = make_float2(acc[mi][ni].z + b0, acc[mi][ni].w + b1);
            if (relu) {
                v0.x = fmaxf(v0.x, 0.f); v0.y = fmaxf(v0.y, 0.f);
                v1.x = fmaxf(v1.x, 0.f); v1.y = fmaxf(v1.y, 0.f);
            }
            if (ra < M)     *(float2*)(C + (size_t)ra * NC + col) = v0;
            if (ra + 8 < M) *(float2*)(C + (size_t)(ra + 8) * NC + col) = v1;
        }
    }
}

// ---------------- launcher ----------------
extern "C" void kernel_launch(void* const* d_in, const int* in_sizes, int n_in,
                              void* d_out, int out_size) {
    const float* x     = (const float*)d_in[0];
    const void*  ei    = d_in[1];
    const float* W_l1  = (const float*)d_in[2];
    const float* b_l1  = (const float*)d_in[3];
    const float* W_r1  = (const float*)d_in[4];
    const float* W_l2  = (const float*)d_in[5];
    const float* b_l2  = (const float*)d_in[6];
    const float* W_r2  = (const float*)d_in[7];
    const float* fc1_W = (const float*)d_in[8];
    const float* fc1_b = (const float*)d_in[9];
    const float* fc2_W = (const float*)d_in[10];
    const float* fc2_b = (const float*)d_in[11];

    float* emb   = (float*)d_out;                       // [N, 64]
    float* recon = (float*)d_out + (size_t)NN * 64;     // [N, 128]

    float* buf; cudaGetSymbolAddress((void**)&buf, g_buf);
    float* h;   cudaGetSymbolAddress((void**)&h, g_h);
    float* bias2; cudaGetSymbolAddress((void**)&bias2, g_bias2);
    __nv_bfloat16* whi; cudaGetSymbolAddress((void**)&whi, g_whi);
    __nv_bfloat16* wlo; cudaGetSymbolAddress((void**)&wlo, g_wlo);

    // CSR build + weight split
    k_prep<<<(WTOT + 255) / 256, 256>>>((const unsigned*)ei, W_l1, W_r1, W_l2, W_r2,
                                        fc1_W, fc2_W, b_l2);
    k_hist<<<(EE + 255) / 256, 256>>>(ei);
    k_scan1<<<NBLK, 1024>>>();
    k_scan2<<<1, 128>>>();
    k_scatter<<<(EE + 255) / 256, 256>>>(ei);

    const int aggBlocks = (NN * 32 + 255) / 256;
    const int gmBlocks  = (NN + 127) / 128;

    // weight segment offsets in g_whi / g_wlo.
    // [W_l2 | W_r2] rows are contiguous at 65536 -> combined 128x256 weight.
    const int oWl1 = 0, oWr1 = 32768, oW2 = 65536, oF1 = 98304, oF2 = 114688;

    // Layer 1: mean1 = agg(x);  h = relu(mean1 @ W_l1^T + x @ W_r1^T + b_l1)
    k_agg128<<<aggBlocks, 256>>>(x, buf);
    k_gemm<128, 4><<<dim3(gmBlocks, 2), 256>>>(
        buf, whi + oWl1, wlo + oWl1, 128,
        x,   whi + oWr1, wlo + oWr1, 128, b_l1, h, NN, 256, 1);

    // Layer 2 (linearity trick): pq = h @ [W_l2;W_r2]^T + [0|b_l2]
    // then emb = mean(p over neighbors) + q
    k_gemm<128, 4><<<dim3(gmBlocks, 1), 256>>>(
        h, whi + oW2, wlo + oW2, 256,
        nullptr, nullptr, nullptr, 0, bias2, buf, NN, 128, 0);
    k_agg_add<<<aggBlocks, 256>>>(buf, emb);

    // Decoder: hid = relu(emb @ fc1_W^T + fc1_b);  recon = hid @ fc2_W^T + fc2_b
    k_gemm<128, 4><<<dim3(gmBlocks, 2), 256>>>(
        emb, whi + oF1, wlo + oF1, 64,
        nullptr, nullptr, nullptr, 0, fc1_b, buf, NN, 256, 1);
    k_gemm<128, 4><<<dim3(gmBlocks, 1), 256>>>(
        buf, whi + oF2, wlo + oF2, 256,
        nullptr, nullptr, nullptr, 0, fc2_b, recon, NN, 128, 0);
}